// round 14
// baseline (speedup 1.0000x reference)
#include <cuda_runtime.h>
#include <cuda_fp16.h>
#include <cstdint>

// Problem constants
#define B_  4
#define L_  2048
#define E_  512
#define H_  8
#define D_  64
#define M_  (B_*L_)
#define MASK_ELEMS ((size_t)B_*L_*L_)
#define LDH 72               // attention smem stride (halves)
#define LDW 40               // gemm smem stride (halves), k-chunk 32
#define EC  0.18033688f      // log2(e)/8
#define PROBE_WORDS (1u<<20) // 4MB sample — safe under every dtype

// ---------------------------------------------------------------------------
// Scratch (device globals; no allocations allowed)
// ---------------------------------------------------------------------------
__device__ __half g_QHh[B_*H_*L_*D_];   // [(b*H+h)][l][d] fp16
__device__ __half g_KHh[B_*H_*L_*D_];
__device__ __half g_VHh[B_*H_*L_*D_];
__device__ float  g_CTX[(size_t)M_*E_]; // [b*L+l][h*D+d]
__device__ float  g_FC [(size_t)M_*E_];
__device__ __half g_Xh[(size_t)M_*E_], g_Xl[(size_t)M_*E_];   // split input
__device__ __half g_Wh16[E_*E_], g_Wl16[E_*E_];               // split weight
__device__ __half g_maskh[MASK_ELEMS];  // 1.0 = keep, 0.0 = masked
__device__ unsigned int g_flagA = 0, g_flagB = 0;

// ---------------------------------------------------------------------------
// PTX helpers
// ---------------------------------------------------------------------------
__device__ __forceinline__ uint32_t smem_u32(const void* p) {
    uint32_t a;
    asm("{ .reg .u64 t; cvta.to.shared.u64 t, %1; cvt.u32.u64 %0, t; }" : "=r"(a) : "l"(p));
    return a;
}
__device__ __forceinline__ uint32_t h2_u32(__half2 h) {
    union { __half2 h; uint32_t u; } cv; cv.h = h; return cv.u;
}
__device__ __forceinline__ void ldsm_x4(uint32_t& r0, uint32_t& r1, uint32_t& r2, uint32_t& r3, uint32_t a) {
    asm volatile("ldmatrix.sync.aligned.m8n8.x4.shared.b16 {%0,%1,%2,%3}, [%4];"
        : "=r"(r0), "=r"(r1), "=r"(r2), "=r"(r3) : "r"(a));
}
__device__ __forceinline__ void ldsm_x4t(uint32_t& r0, uint32_t& r1, uint32_t& r2, uint32_t& r3, uint32_t a) {
    asm volatile("ldmatrix.sync.aligned.m8n8.x4.trans.shared.b16 {%0,%1,%2,%3}, [%4];"
        : "=r"(r0), "=r"(r1), "=r"(r2), "=r"(r3) : "r"(a));
}
__device__ __forceinline__ void mma_f16(float* c, const uint32_t* a, uint32_t b0, uint32_t b1) {
    asm volatile("mma.sync.aligned.m16n8k16.row.col.f32.f16.f16.f32 "
        "{%0,%1,%2,%3}, {%4,%5,%6,%7}, {%8,%9}, {%0,%1,%2,%3};"
        : "+f"(c[0]), "+f"(c[1]), "+f"(c[2]), "+f"(c[3])
        : "r"(a[0]), "r"(a[1]), "r"(a[2]), "r"(a[3]), "r"(b0), "r"(b1));
}

// ---------------------------------------------------------------------------
// Mask dtype probe (4MB sample) + fp16 canonicalize
// ---------------------------------------------------------------------------
__global__ __launch_bounds__(256) void probe_mask(const unsigned int* __restrict__ mw)
{
    size_t i = (size_t)blockIdx.x * blockDim.x + threadIdx.x;
    unsigned int w = mw[i];
    unsigned int a = (w != 0u && w != 1u) ? 1u : 0u;
    unsigned int b = (w != 0u && w != 0x3F800000u) ? 1u : 0u;
    for (int o = 16; o > 0; o >>= 1) {
        a |= __shfl_xor_sync(0xffffffffu, a, o);
        b |= __shfl_xor_sync(0xffffffffu, b, o);
    }
    if ((threadIdx.x & 31) == 0) {
        if (a) atomicOr(&g_flagA, 1u);
        if (b) atomicOr(&g_flagB, 1u);
    }
}

__global__ __launch_bounds__(256) void convert_mask(const void* __restrict__ mraw)
{
    size_t i = (size_t)blockIdx.x * blockDim.x + threadIdx.x;
    unsigned char v;
    if (!g_flagA)       v = (unsigned char)(((const int*)mraw)[i] != 0);
    else if (!g_flagB)  v = (unsigned char)(((const float*)mraw)[i] != 0.f);
    else                v = (unsigned char)(((const unsigned char*)mraw)[i] != 0);
    g_maskh[i] = __float2half(v ? 0.f : 1.f);   // multiplier: masked -> 0
}

// ---------------------------------------------------------------------------
// Split fp32 -> (hi, lo) fp16 pair for X [8192x512] and W [512x512].
// X == nullptr -> read g_CTX.
// ---------------------------------------------------------------------------
#define XU (size_t)((size_t)M_*E_/4)       // 1,048,576 float4 units
#define WU (E_*E_/4)                       // 65,536 units
__global__ __launch_bounds__(256) void split_pair(const float* __restrict__ X,
                                                  const float* __restrict__ W)
{
    size_t i = (size_t)blockIdx.x * blockDim.x + threadIdx.x;
    const float* src; __half* dh; __half* dl; size_t o;
    if (i < XU) { src = X ? X : (const float*)g_CTX; o = i;      dh = g_Xh;  dl = g_Xl;  }
    else        { src = W;                           o = i - XU; dh = g_Wh16; dl = g_Wl16; }
    float4 f = ((const float4*)src)[o];
    __half hx = __float2half(f.x), hy = __float2half(f.y);
    __half hz = __float2half(f.z), hw = __float2half(f.w);
    __half lx = __float2half(f.x - __half2float(hx));
    __half ly = __float2half(f.y - __half2float(hy));
    __half lz = __float2half(f.z - __half2float(hz));
    __half lw = __float2half(f.w - __half2float(hw));
    __half2* ph = (__half2*)(dh + o*4);
    __half2* pl = (__half2*)(dl + o*4);
    ph[0] = __halves2half2(hx, hy); ph[1] = __halves2half2(hz, hw);
    pl[0] = __halves2half2(lx, ly); pl[1] = __halves2half2(lz, lw);
}

// ---------------------------------------------------------------------------
// Projection GEMM via split-fp16 mma.sync: C = Xhi*Whi + Xhi*Wlo + Xlo*Whi
// (+bias). 128x128 tile, 8 warps (4m x 2n), warp tile 32m x 64n, k-chunk 32.
// LAYOUT 1: head-split scatter to fp16 (dst_sel 0/1/2); LAYOUT 0: fp32 g_FC.
// ---------------------------------------------------------------------------
template<int LAYOUT>
__global__ __launch_bounds__(256) void gemm_mma(const float* __restrict__ bias, int dst_sel)
{
    __shared__ __half sAh[128*LDW], sAl[128*LDW];
    __shared__ __half sWh[128*LDW], sWl[128*LDW];

    const int tid = threadIdx.x, w = tid >> 5, lane = tid & 31;
    const int g = lane >> 2, t = lane & 3;
    const int wm = w & 3, wn = w >> 2;
    const int m0 = blockIdx.x * 128, n0 = blockIdx.y * 128;

    const int rr_a = (lane & 7) + ((lane & 8) ? 8 : 0), cc_a = (lane & 16) ? 8 : 0;
    const int rr_b = (lane & 7) + ((lane & 16) ? 8 : 0), cc_b = (lane & 8) ? 8 : 0;
    const uint32_t ahb = smem_u32(sAh), alb = smem_u32(sAl);
    const uint32_t whb = smem_u32(sWh), wlb = smem_u32(sWl);

    float acc[2][8][4] = {};

    const int lrow = tid >> 2, lu = (tid & 3) * 8;
    for (int kc = 0; kc < 16; kc++) {
        #pragma unroll
        for (int it = 0; it < 2; it++) {
            int row = lrow + it*64;
            size_t ga = (size_t)(m0 + row) * E_ + kc*32 + lu;
            size_t gw = (size_t)(n0 + row) * E_ + kc*32 + lu;
            *(uint4*)&sAh[row*LDW + lu] = *(const uint4*)&g_Xh[ga];
            *(uint4*)&sAl[row*LDW + lu] = *(const uint4*)&g_Xl[ga];
            *(uint4*)&sWh[row*LDW + lu] = *(const uint4*)&g_Wh16[gw];
            *(uint4*)&sWl[row*LDW + lu] = *(const uint4*)&g_Wl16[gw];
        }
        __syncthreads();
        #pragma unroll
        for (int ks = 0; ks < 2; ks++) {
            uint32_t ah[2][4], al[2][4];
            #pragma unroll
            for (int mf = 0; mf < 2; mf++) {
                uint32_t off = (uint32_t)((32*wm + 16*mf + rr_a)*LDW + ks*16 + cc_a) * 2;
                ldsm_x4(ah[mf][0], ah[mf][1], ah[mf][2], ah[mf][3], ahb + off);
                ldsm_x4(al[mf][0], al[mf][1], al[mf][2], al[mf][3], alb + off);
            }
            #pragma unroll
            for (int p = 0; p < 4; p++) {
                uint32_t wh[4], wl[4];
                uint32_t off = (uint32_t)((64*wn + 16*p + rr_b)*LDW + ks*16 + cc_b) * 2;
                ldsm_x4(wh[0], wh[1], wh[2], wh[3], whb + off);
                ldsm_x4(wl[0], wl[1], wl[2], wl[3], wlb + off);
                #pragma unroll
                for (int mf = 0; mf < 2; mf++) {
                    mma_f16(acc[mf][2*p],   ah[mf], wh[0], wh[1]);
                    mma_f16(acc[mf][2*p],   ah[mf], wl[0], wl[1]);
                    mma_f16(acc[mf][2*p],   al[mf], wh[0], wh[1]);
                    mma_f16(acc[mf][2*p+1], ah[mf], wh[2], wh[3]);
                    mma_f16(acc[mf][2*p+1], ah[mf], wl[2], wl[3]);
                    mma_f16(acc[mf][2*p+1], al[mf], wh[2], wh[3]);
                }
            }
        }
        __syncthreads();
    }

    // Epilogue
    float2 bb[8];
    #pragma unroll
    for (int nf = 0; nf < 8; nf++) {
        int n = n0 + 64*wn + nf*8 + 2*t;
        bb[nf] = make_float2(bias[n], bias[n+1]);
    }
    __half* hdst = (dst_sel == 0) ? g_QHh : (dst_sel == 1) ? g_KHh : g_VHh;
    #pragma unroll
    for (int mf = 0; mf < 2; mf++) {
        #pragma unroll
        for (int hh = 0; hh < 2; hh++) {
            int m = m0 + 32*wm + 16*mf + g + 8*hh;
            #pragma unroll
            for (int nf = 0; nf < 8; nf++) {
                float v0 = acc[mf][nf][2*hh]   + bb[nf].x;
                float v1 = acc[mf][nf][2*hh+1] + bb[nf].y;
                int n = n0 + 64*wn + nf*8 + 2*t;
                if (LAYOUT == 0) {
                    *(float2*)&g_FC[(size_t)m * E_ + n] = make_float2(v0, v1);
                } else {
                    int b = m >> 11, l = m & (L_-1), h = n >> 6, d = n & 63;
                    *(__half2*)&hdst[(((size_t)(b*H_ + h) * L_) + l) * D_ + d] =
                        __floats2half2_rn(v0, v1);
                }
            }
        }
    }
}

// ---------------------------------------------------------------------------
// Attention via raw mma.sync m16n8k16 fp16 (fp32 accum), two passes over K.
// QKV already fp16 in head-split layout. Structure proven in R13.
// ---------------------------------------------------------------------------
__global__ __launch_bounds__(256, 2) void attn_mma(float* __restrict__ attn)
{
    const int tid = threadIdx.x, w = tid >> 5, lane = tid & 31;
    const int g = lane >> 2, t = lane & 3;
    const int bh = blockIdx.x, b = bh >> 3, h = bh & 7;
    const int q0 = blockIdx.y * 128;
    const int m0 = 16 * w;

    __shared__ __half Qs[128*LDH];
    __shared__ __half Ks[64*LDH];
    __shared__ __half Vs[64*LDH];
    __shared__ float s_inv[128];

    const __half* Qb = g_QHh + (size_t)bh * (L_*D_) + (size_t)q0 * D_;
    const __half* Kb = g_KHh + (size_t)bh * (L_*D_);
    const __half* Vb = g_VHh + (size_t)bh * (L_*D_);

    // Fill Q (already fp16): 128 rows x 64 halves
    #pragma unroll
    for (int it = 0; it < 4; it++) {
        int idx = tid + it*256;
        int row = idx >> 3, u = (idx & 7) * 8;
        *(uint4*)&Qs[row*LDH + u] = *(const uint4*)(Qb + (size_t)row * D_ + u);
    }
    __syncthreads();

    // Hoisted Q A-fragments: 4 k16 blocks over d=64
    uint32_t qf[4][4];
    {
        uint32_t base = smem_u32(Qs);
        int rr = m0 + (lane & 7) + ((lane & 8) ? 8 : 0);
        int cc = (lane & 16) ? 8 : 0;
        #pragma unroll
        for (int j = 0; j < 4; j++)
            ldsm_x4(qf[j][0], qf[j][1], qf[j][2], qf[j][3],
                    base + (uint32_t)(rr*LDH + 16*j + cc) * 2);
    }

    const size_t mrow_lo = ((size_t)b*L_ + q0 + m0 + g) * L_;
    const size_t mrow_hi = mrow_lo + (size_t)8*L_;
    float* arow_lo = attn + ((size_t)(h*B_ + b)*L_ + q0 + m0 + g) * L_;
    float* arow_hi = arow_lo + (size_t)8*L_;

    const uint32_t ksb = smem_u32(Ks);
    const uint32_t vsb = smem_u32(Vs);
    const int krr = (lane & 7) + ((lane & 16) ? 8 : 0);
    const int kcc = (lane & 8) ? 8 : 0;
    const int vrr = lane & 15;
    const int vcc = (lane & 16) ? 8 : 0;

    #define FILL_K(kt) do { \
        const __half* Kt_ = Kb + (size_t)(kt)*64*D_; \
        _Pragma("unroll") \
        for (int it = 0; it < 2; it++) { \
            int idx = tid + it*256; \
            int row = idx >> 3, u = (idx & 7) * 8; \
            *(uint4*)&Ks[row*LDH + u] = *(const uint4*)(Kt_ + (size_t)row * D_ + u); \
        } } while (0)

    #define FILL_V(kt) do { \
        const __half* Vt_ = Vb + (size_t)(kt)*64*D_; \
        _Pragma("unroll") \
        for (int it = 0; it < 2; it++) { \
            int idx = tid + it*256; \
            int row = idx >> 3, u = (idx & 7) * 8; \
            *(uint4*)&Vs[row*LDH + u] = *(const uint4*)(Vt_ + (size_t)row * D_ + u); \
        } } while (0)

    #define COMPUTE_S(S) do { \
        _Pragma("unroll") \
        for (int p = 0; p < 4; p++) { \
            uint32_t kf[4][4]; \
            _Pragma("unroll") \
            for (int j = 0; j < 4; j++) \
                ldsm_x4(kf[j][0], kf[j][1], kf[j][2], kf[j][3], \
                        ksb + (uint32_t)((16*p + krr)*LDH + 16*j + kcc) * 2); \
            _Pragma("unroll") \
            for (int j = 0; j < 4; j++) { \
                mma_f16(S[2*p],   qf[j], kf[j][0], kf[j][1]); \
                mma_f16(S[2*p+1], qf[j], kf[j][2], kf[j][3]); \
            } \
        } } while (0)

    // ---------------- Pass A: row sums ----------------
    float rs_lo = 0.f, rs_hi = 0.f;
    for (int kt = 0; kt < 32; kt++) {
        FILL_K(kt);
        __syncthreads();
        float S[8][4] = {};
        COMPUTE_S(S);
        __syncthreads();
        int colb = kt*64 + 2*t;
        #pragma unroll
        for (int n = 0; n < 8; n++) {
            int col = colb + n*8;
            __half2 mlo = *(const __half2*)&g_maskh[mrow_lo + col];
            __half2 mhi = *(const __half2*)&g_maskh[mrow_hi + col];
            rs_lo += exp2f(S[n][0]*EC) * __low2float(mlo) + exp2f(S[n][1]*EC) * __high2float(mlo);
            rs_hi += exp2f(S[n][2]*EC) * __low2float(mhi) + exp2f(S[n][3]*EC) * __high2float(mhi);
        }
    }
    rs_lo += __shfl_xor_sync(0xffffffffu, rs_lo, 1);
    rs_lo += __shfl_xor_sync(0xffffffffu, rs_lo, 2);
    rs_hi += __shfl_xor_sync(0xffffffffu, rs_hi, 1);
    rs_hi += __shfl_xor_sync(0xffffffffu, rs_hi, 2);
    if (t == 0) { s_inv[m0+g] = 1.f/rs_lo; s_inv[m0+g+8] = 1.f/rs_hi; }
    __syncthreads();
    const float iv_lo = s_inv[m0+g], iv_hi = s_inv[m0+g+8];

    // ---------------- Pass B: attn write + PV ----------------
    float ctx[8][4] = {};
    for (int kt = 0; kt < 32; kt++) {
        FILL_K(kt);
        FILL_V(kt);
        __syncthreads();
        float S[8][4] = {};
        COMPUTE_S(S);

        uint32_t pf[4][4];
        int colb = kt*64 + 2*t;
        #pragma unroll
        for (int n = 0; n < 8; n++) {
            int col = colb + n*8;
            __half2 mlo = *(const __half2*)&g_maskh[mrow_lo + col];
            __half2 mhi = *(const __half2*)&g_maskh[mrow_hi + col];
            float e0 = exp2f(S[n][0]*EC) * __low2float(mlo)  * iv_lo;
            float e1 = exp2f(S[n][1]*EC) * __high2float(mlo) * iv_lo;
            float e2 = exp2f(S[n][2]*EC) * __low2float(mhi)  * iv_hi;
            float e3 = exp2f(S[n][3]*EC) * __high2float(mhi) * iv_hi;
            *(float2*)&arow_lo[col] = make_float2(e0, e1);
            *(float2*)&arow_hi[col] = make_float2(e2, e3);
            pf[n>>1][(n&1)*2 + 0] = h2_u32(__floats2half2_rn(e0, e1));
            pf[n>>1][(n&1)*2 + 1] = h2_u32(__floats2half2_rn(e2, e3));
        }

        #pragma unroll
        for (int j = 0; j < 4; j++) {
            #pragma unroll
            for (int p = 0; p < 4; p++) {
                uint32_t v0, v1, v2, v3;
                ldsm_x4t(v0, v1, v2, v3,
                         vsb + (uint32_t)((16*j + vrr)*LDH + 16*p + vcc) * 2);
                mma_f16(ctx[2*p],   pf[j], v0, v1);
                mma_f16(ctx[2*p+1], pf[j], v2, v3);
            }
        }
        __syncthreads();
    }

    // ctx epilogue (P already normalized)
    float* cp_lo = g_CTX + ((size_t)b*L_ + q0 + m0 + g) * E_ + h*64;
    float* cp_hi = cp_lo + (size_t)8*E_;
    #pragma unroll
    for (int nd = 0; nd < 8; nd++) {
        *(float2*)&cp_lo[nd*8 + 2*t] = make_float2(ctx[nd][0], ctx[nd][1]);
        *(float2*)&cp_hi[nd*8 + 2*t] = make_float2(ctx[nd][2], ctx[nd][3]);
    }
}

// ---------------------------------------------------------------------------
// Fused residual + LayerNorm, warp-per-row (no block barriers).
// ---------------------------------------------------------------------------
__global__ __launch_bounds__(256) void ln2_kernel(
    const float* __restrict__ resid, const float* __restrict__ gamma,
    const float* __restrict__ beta, float* __restrict__ out)
{
    const int row = blockIdx.x * 8 + (threadIdx.x >> 5);
    const int lane = threadIdx.x & 31;
    const float4* fc4 = (const float4*)(g_FC + (size_t)row * E_);
    const float4* rs4 = (const float4*)(resid + (size_t)row * E_);

    float4 x[4];
    float s = 0.f, sq = 0.f;
    #pragma unroll
    for (int i = 0; i < 4; i++) {
        float4 a = fc4[i*32 + lane], r = rs4[i*32 + lane];
        x[i] = make_float4(a.x+r.x, a.y+r.y, a.z+r.z, a.w+r.w);
        s  += (x[i].x + x[i].y) + (x[i].z + x[i].w);
        sq += (x[i].x*x[i].x + x[i].y*x[i].y) + (x[i].z*x[i].z + x[i].w*x[i].w);
    }
    #pragma unroll
    for (int o = 16; o > 0; o >>= 1) {
        s  += __shfl_xor_sync(0xffffffffu, s,  o);
        sq += __shfl_xor_sync(0xffffffffu, sq, o);
    }
    float mu = s * (1.f / E_);
    float rstd = rsqrtf(sq * (1.f / E_) - mu*mu + 1e-5f);
    float4* o4 = (float4*)(out + (size_t)row * E_);
    const float4* g4 = (const float4*)gamma;
    const float4* b4 = (const float4*)beta;
    #pragma unroll
    for (int i = 0; i < 4; i++) {
        float4 gg = g4[i*32 + lane], bb = b4[i*32 + lane];
        o4[i*32 + lane] = make_float4((x[i].x-mu)*rstd*gg.x + bb.x,
                                      (x[i].y-mu)*rstd*gg.y + bb.y,
                                      (x[i].z-mu)*rstd*gg.z + bb.z,
                                      (x[i].w-mu)*rstd*gg.w + bb.w);
    }
}

// ---------------------------------------------------------------------------
extern "C" void kernel_launch(void* const* d_in, const int* in_sizes, int n_in,
                              void* d_out, int out_size)
{
    const float* q    = (const float*)d_in[0];
    const float* k    = (const float*)d_in[1];
    const float* v    = (const float*)d_in[2];
    const void*  mask = d_in[3];
    const float* Wq   = (const float*)d_in[4];
    const float* bq   = (const float*)d_in[5];
    const float* Wk   = (const float*)d_in[6];
    const float* bk   = (const float*)d_in[7];
    const float* Wv   = (const float*)d_in[8];
    const float* bv   = (const float*)d_in[9];
    const float* Wfc  = (const float*)d_in[10];
    const float* bfc  = (const float*)d_in[11];
    const float* gamma= (const float*)d_in[12];
    const float* beta = (const float*)d_in[13];

    float* out  = (float*)d_out;
    float* attn = out + (size_t)M_ * E_;

    const int SPLIT_GRID = (int)((XU + WU) / 256);   // 4352
    dim3 gproj(M_/128, E_/128);                      // (64, 4)

    split_pair<<<SPLIT_GRID, 256>>>(q, Wq);          // 1
    gemm_mma<1><<<gproj, 256>>>(bq, 0);              // 2
    split_pair<<<SPLIT_GRID, 256>>>(k, Wk);          // 3
    gemm_mma<1><<<gproj, 256>>>(bk, 1);              // 4  <-- profiled
    split_pair<<<SPLIT_GRID, 256>>>(v, Wv);          // 5
    gemm_mma<1><<<gproj, 256>>>(bv, 2);              // 6

    probe_mask<<<PROBE_WORDS/256, 256>>>((const unsigned int*)mask);  // 7
    convert_mask<<<MASK_ELEMS/256, 256>>>(mask);                      // 8

    dim3 gattn(B_*H_, L_/128);                       // (32, 16)
    attn_mma<<<gattn, 256>>>(attn);                  // 9

    split_pair<<<SPLIT_GRID, 256>>>(nullptr, Wfc);   // 10 (g_CTX)
    gemm_mma<0><<<gproj, 256>>>(bfc, 3);             // 11

    ln2_kernel<<<M_/8, 256>>>(q, gamma, beta, out);  // 12
}